// round 15
// baseline (speedup 1.0000x reference)
#include <cuda_runtime.h>
#include <cstdint>

// ACoef: per-sample traces of x^2..x^11 for 65536 16x16 fp32 matrices,
// out[b] = sum_{i,j} coef[i][j] * tr_{i+2}^(j+1) / 256^(i+j+1).
//
// One sample per WARP ITERATION, bf16 m16n8k16 mma, 3xBF16 compensation.
// Chain: x2=X*X, x3=X*x2, x5=x3*x2, x6=x3*x3.
// R15:
//  (1) PERSISTENT grid (148*8 CTAs, grid-stride warp loop): R14 ran ~14
//      waves of 0.36us CTAs; wave transitions (~2360 cyc each) accounted
//      for the 43%-vs-67% occupancy gap. One wave now.
//  (2) Bc3 = in-lane split of T3 (B-frag(M) == A-frag(M^T) == in-lane
//      repack of C-frag(M^T)); second conv_to_B deleted.
//
// bf16 m16n8k16 fragments (lane: g=lane>>2, t=lane&3):
//   A: a0={A[g][2t],..} a1={A[g+8][2t],..} a2={A[g][2t+8],..} a3={A[g+8][2t+8],..}
//   B: b_kk={B[2t+8kk][8nn+g],B[2t+8kk+1][8nn+g]}  (col-major)
//   C: CH[nn][0]=M[g][8nn+2t] CH[nn][1]=M[g][8nn+2t+1]
//      CH[nn][2]=M[g+8][8nn+2t] CH[nn][3]=M[g+8][8nn+2t+1]   (fp32)

__device__ __forceinline__ uint32_t pack2(float e0, float e1) {
    uint32_t r;
    asm("cvt.rn.bf16x2.f32 %0, %1, %2;" : "=r"(r) : "f"(e1), "f"(e0));
    return r;
}
__device__ __forceinline__ void split_pair(float v0, float v1, uint32_t& hi, uint32_t& lo) {
    hi = pack2(v0, v1);
    float h0 = __uint_as_float(hi << 16);
    float h1 = __uint_as_float(hi & 0xFFFF0000u);
    lo = pack2(v0 - h0, v1 - h1);
}
__device__ __forceinline__ uint32_t prmt1(uint32_t a, uint32_t sel) {
    uint32_t r;
    asm("prmt.b32 %0, %1, %1, %2;" : "=r"(r) : "r"(a), "r"(sel));
    return r;
}
__device__ __forceinline__ void mma_bf16(float d[4], const uint32_t a[4],
                                         const uint32_t b[2], const float c[4]) {
    asm volatile(
        "mma.sync.aligned.m16n8k16.row.col.f32.bf16.bf16.f32 "
        "{%0,%1,%2,%3}, {%4,%5,%6,%7}, {%8,%9}, {%10,%11,%12,%13};"
        : "=f"(d[0]), "=f"(d[1]), "=f"(d[2]), "=f"(d[3])
        : "r"(a[0]), "r"(a[1]), "r"(a[2]), "r"(a[3]),
          "r"(b[0]), "r"(b[1]),
          "f"(c[0]), "f"(c[1]), "f"(c[2]), "f"(c[3]));
}
__device__ __forceinline__ float shfl(float v, int src) {
    return __shfl_sync(0xffffffffu, v, src);
}

// C-frag -> bf16 B-frags via shuffles (used for Bc2 only).
__device__ __forceinline__ void conv_to_B(const float CH[2][4], int idxA, int idxB,
                                          bool godd, uint32_t psel,
                                          uint32_t Bhi[2][2], uint32_t Blo[2][2]) {
#pragma unroll
    for (int nn = 0; nn < 2; nn++)
#pragma unroll
        for (int kk = 0; kk < 2; kk++) {
            float z1 = godd ? CH[nn][2 * kk + 1] : CH[nn][2 * kk];
            float s1 = shfl(z1, idxA);
            float z2 = godd ? CH[nn][2 * kk] : CH[nn][2 * kk + 1];
            float s2 = shfl(z2, idxB);
            uint32_t p = pack2(s1, s2);
            float d1 = s1 - __uint_as_float(p << 16);
            float d2 = s2 - __uint_as_float(p & 0xFFFF0000u);
            uint32_t qq = pack2(d1, d2);
            Bhi[nn][kk] = prmt1(p, psel);
            Blo[nn][kk] = prmt1(qq, psel);
        }
}

// Register transpose: TH = C-frag layout of M^T given CH of M (fp32).
__device__ __forceinline__ void transpose_frag(const float CH[2][4], int idxA, int idxB,
                                               bool godd, float TH[2][4]) {
#pragma unroll
    for (int nn = 0; nn < 2; nn++)
#pragma unroll
        for (int h = 0; h < 2; h++) {
            float z1 = godd ? CH[h][2 * nn + 1] : CH[h][2 * nn];
            float s1 = shfl(z1, idxA);
            float z2 = godd ? CH[h][2 * nn] : CH[h][2 * nn + 1];
            float s2 = shfl(z2, idxB);
            TH[nn][2 * h + 0] = godd ? s2 : s1;
            TH[nn][2 * h + 1] = godd ? s1 : s2;
        }
}

__device__ __forceinline__ float diag_partial(const float CH[2][4], bool isdiag, bool godd) {
    float e0 = godd ? CH[0][1] : CH[0][0];
    float e1 = godd ? CH[1][3] : CH[1][2];
    return isdiag ? (e0 + e1) : 0.f;
}

__device__ __forceinline__ float frag_dot(const float A[2][4], const float B[2][4]) {
    float s = 0.f;
#pragma unroll
    for (int nn = 0; nn < 2; nn++)
#pragma unroll
        for (int r = 0; r < 4; r++) s = fmaf(A[nn][r], B[nn][r], s);
    return s;
}

__device__ __forceinline__ void mm_chain(const uint32_t Ahi[4], const uint32_t Alo[4],
                                         const uint32_t Bhi[2][2], const uint32_t Blo[2][2],
                                         float D[2][4]) {
#pragma unroll
    for (int nn = 0; nn < 2; nn++) {
        float d[4] = {0.f, 0.f, 0.f, 0.f};
        mma_bf16(d, Ahi, Blo[nn], d);
        mma_bf16(d, Alo, Bhi[nn], d);
        mma_bf16(d, Ahi, Bhi[nn], d);
#pragma unroll
        for (int r = 0; r < 4; r++) D[nn][r] = d[r];
    }
}

#define NBLOCKS 1184   // 148 SMs * 8 resident CTAs -> single wave

__global__ void __launch_bounds__(128)
acoef_kernel(const float* __restrict__ x, const float* __restrict__ coef,
             float* __restrict__ out, int nsamples) {
    const int lane = threadIdx.x & 31;
    const int g = lane >> 2;
    const int t = lane & 3;
    const int q = g >> 1;
    const bool godd = (g & 1);
    const bool hi16 = (lane & 16);
    const bool isdiag = (t == q);
    const uint32_t psel = godd ? 0x1032u : 0x3210u;

    const int idxA_t = 8 * t + q + (godd ? 4 : 0);
    const int idxB_t = idxA_t ^ 4;

    const bool b8 = (lane & 8);
    const bool b4 = (lane & 4);
    const bool b2 = (lane & 2);
    // polynomial lane assignment (constant per lane)
    const int pidx = (hi16 ? 5 : 0) + (b8 ? (b4 ? 4 : 3) : (b4 ? 2 : (b2 ? 1 : 0)));
    const bool pactive = ((lane & 1) == 0) &&
                         (((lane & 2) == 0) || ((lane & 12) == 0));
    const float4 cf = __ldg((const float4*)coef + pidx);
    const float pscale = __uint_as_float((uint32_t)(127 - 8 * pidx) << 23); // 256^-i

    const int warpsTotal = NBLOCKS * 4;
    const int warpGlobal = blockIdx.x * 4 + (threadIdx.x >> 5);

#pragma unroll 1
    for (long sample = warpGlobal; sample < nsamples; sample += warpsTotal) {
        const float* gx = x + sample * 256;

        // ---- A(X): 4 x LDG.64; doubles as W = C-frag(X) for tr4 dot ----
        float W[2][4];
        uint32_t AXhi[4], AXlo[4];
        {
            float2 p00 = __ldg((const float2*)(gx + g * 16 + 2 * t));
            float2 p10 = __ldg((const float2*)(gx + (g + 8) * 16 + 2 * t));
            float2 p01 = __ldg((const float2*)(gx + g * 16 + 2 * t + 8));
            float2 p11 = __ldg((const float2*)(gx + (g + 8) * 16 + 2 * t + 8));
            W[0][0] = p00.x; W[0][1] = p00.y; W[0][2] = p10.x; W[0][3] = p10.y;
            W[1][0] = p01.x; W[1][1] = p01.y; W[1][2] = p11.x; W[1][3] = p11.y;
            split_pair(p00.x, p00.y, AXhi[0], AXlo[0]);
            split_pair(p10.x, p10.y, AXhi[1], AXlo[1]);
            split_pair(p01.x, p01.y, AXhi[2], AXlo[2]);
            split_pair(p11.x, p11.y, AXhi[3], AXlo[3]);
        }
        // ---- B(X): b_kk = {X[2t+8kk][8nn+g], X[2t+8kk+1][8nn+g]} ----
        uint32_t BXhi[2][2], BXlo[2][2];
#pragma unroll
        for (int nn = 0; nn < 2; nn++)
#pragma unroll
            for (int kk = 0; kk < 2; kk++) {
                const int col = 8 * nn + g;
                const int k0 = 2 * t + 8 * kk;
                float v0 = __ldg(gx + k0 * 16 + col);
                float v1 = __ldg(gx + (k0 + 1) * 16 + col);
                split_pair(v0, v1, BXhi[nn][kk], BXlo[nn][kk]);
            }

        float V[10];
        float C2[2][4], C3[2][4], C5[2][4], C6[2][4];
        float T3[2][4], T5[2][4];

        // mm1: x2 = X*X
        mm_chain(AXhi, AXlo, BXhi, BXlo, C2);
        V[0] = diag_partial(C2, isdiag, godd);          // tr2

        // B(x2) via conv; C2 stays live (tr7 = <T5,C2>)
        uint32_t Bc2hi[2][2], Bc2lo[2][2];
        conv_to_B(C2, idxA_t, idxB_t, godd, psel, Bc2hi, Bc2lo);

        // mm2: x3 = X*x2
        mm_chain(AXhi, AXlo, Bc2hi, Bc2lo, C3);
        V[1] = diag_partial(C3, isdiag, godd);          // tr3

        // T3; tr4 = <W, T3>
        transpose_frag(C3, idxA_t, idxB_t, godd, T3);
        V[2] = frag_dot(W, T3);                         // tr4

        // A3 = in-lane repack of C3; Bc3 = in-lane repack of T3
        uint32_t A3hi[4], A3lo[4];
        split_pair(C3[0][0], C3[0][1], A3hi[0], A3lo[0]);
        split_pair(C3[0][2], C3[0][3], A3hi[1], A3lo[1]);
        split_pair(C3[1][0], C3[1][1], A3hi[2], A3lo[2]);
        split_pair(C3[1][2], C3[1][3], A3hi[3], A3lo[3]);
        uint32_t Bc3hi[2][2], Bc3lo[2][2];
        split_pair(T3[0][0], T3[0][1], Bc3hi[0][0], Bc3lo[0][0]);  // nn0 kk0
        split_pair(T3[0][2], T3[0][3], Bc3hi[1][0], Bc3lo[1][0]);  // nn1 kk0
        split_pair(T3[1][0], T3[1][1], Bc3hi[0][1], Bc3lo[0][1]);  // nn0 kk1
        split_pair(T3[1][2], T3[1][3], Bc3hi[1][1], Bc3lo[1][1]);  // nn1 kk1

        // mm3: x5 = x3*x2
        mm_chain(A3hi, A3lo, Bc2hi, Bc2lo, C5);
        V[3] = diag_partial(C5, isdiag, godd);          // tr5
        V[6] = frag_dot(T3, C5);                        // tr8 = tr(x3*x5)

        // mm4: x6 = x3*x3
        mm_chain(A3hi, A3lo, Bc3hi, Bc3lo, C6);
        V[4] = diag_partial(C6, isdiag, godd);          // tr6
        V[7] = frag_dot(T3, C6);                        // tr9 = tr(x3*x6)

        // T5; tr7 = <T5, C2>
        transpose_frag(C5, idxA_t, idxB_t, godd, T5);
        V[5] = frag_dot(T5, C2);                        // tr7
        V[8] = frag_dot(T5, C5);                        // tr10
        V[9] = frag_dot(T5, C6);                        // tr11

        // ---- 10-value reduce-scatter: 5/3/2/1/1 halving, 12 shfl ----
#pragma unroll
        for (int k = 0; k < 5; k++) {
            float send = hi16 ? V[k] : V[k + 5];
            float recv = __shfl_xor_sync(0xffffffffu, send, 16);
            V[k] = (hi16 ? V[k + 5] : V[k]) + recv;
        }
#pragma unroll
        for (int k = 0; k < 2; k++) {
            float send = b8 ? V[k] : V[k + 3];
            float recv = __shfl_xor_sync(0xffffffffu, send, 8);
            V[k] = (b8 ? V[k + 3] : V[k]) + recv;
        }
        {
            float recv = __shfl_xor_sync(0xffffffffu, V[2], 8);
            V[2] = V[2] + recv;   // valid in b8=0 lanes
        }
        {
            float send = b4 ? V[0] : (b8 ? V[1] : V[2]);
            float recv = __shfl_xor_sync(0xffffffffu, send, 4);
            float keep = b4 ? (b8 ? V[1] : V[2]) : V[0];
            V[0] = keep + recv;
        }
        {
            float recv = __shfl_xor_sync(0xffffffffu, V[1], 4);
            V[1] = V[1] + recv;   // valid in b8=0, b4=0 lanes
        }
        {
            const bool g00 = !b8 && !b4;
            float send = (g00 && !b2) ? V[1] : V[0];
            float recv = __shfl_xor_sync(0xffffffffu, send, 2);
            float keep = (g00 && b2) ? V[1] : V[0];
            V[0] = keep + recv;
        }
        V[0] += __shfl_xor_sync(0xffffffffu, V[0], 1);

        // ---- distributed polynomial ----
        {
            const float u  = V[0] * (1.0f / 256.0f);
            const float u2 = u * u;
            float term = cf.x * u + cf.y * u2 + cf.z * (u2 * u) + cf.w * (u2 * u2);
            term *= pscale;
            term = pactive ? term : 0.f;
            term += __shfl_xor_sync(0xffffffffu, term, 16);
            term += __shfl_xor_sync(0xffffffffu, term, 8);
            term += __shfl_xor_sync(0xffffffffu, term, 4);
            term += __shfl_xor_sync(0xffffffffu, term, 2);
            if (lane == 0) out[sample] = term;
        }
    }
}

extern "C" void kernel_launch(void* const* d_in, const int* in_sizes, int n_in,
                              void* d_out, int out_size) {
    const float* x;
    const float* coef;
    if (n_in >= 2 && in_sizes[0] == 40) {
        coef = (const float*)d_in[0];
        x    = (const float*)d_in[1];
    } else {
        x    = (const float*)d_in[0];
        coef = (const float*)d_in[1];
    }
    float* out = (float*)d_out;
    int nsamples = out_size;
    acoef_kernel<<<NBLOCKS, 128>>>(x, coef, out, nsamples);
}

// round 16
// speedup vs baseline: 1.0094x; 1.0094x over previous
#include <cuda_runtime.h>
#include <cstdint>

// ACoef: per-sample traces of x^2..x^11 for 65536 16x16 fp32 matrices,
// out[b] = sum_{i,j} coef[i][j] * tr_{i+2}^(j+1) / 256^(i+j+1).
//
// One sample per WARP, bf16 m16n8k16 mma, 3xBF16 compensation
// (AhiBlo + AloBhi + AhiBhi), 6 mma per matmul.
// Chain: x2=X*X, x3=X*x2, x5=x3*x2, x6=x3*x3.
// R16 (on the R14 non-persistent base; R15's persistent grid regressed):
//  - BX = conv_to_B(W): W (the A-load data) IS the C-frag of X, so the
//    B-fragment of X comes from the existing conv machinery. Deletes the
//    8 strided B LDGs + 4 split_pairs; each matrix is now read from DRAM
//    exactly once, fully coalesced. Bit-identical math.
//  - mm4 moved after T5/tr7 so C2 dies before C6 is live (lower peak regs).
//
// bf16 m16n8k16 fragments (lane: g=lane>>2, t=lane&3):
//   A: a0={A[g][2t],..} a1={A[g+8][2t],..} a2={A[g][2t+8],..} a3={A[g+8][2t+8],..}
//   B: b_kk={B[2t+8kk][8nn+g],B[2t+8kk+1][8nn+g]}  (col-major)
//   C: CH[nn][0]=M[g][8nn+2t] CH[nn][1]=M[g][8nn+2t+1]
//      CH[nn][2]=M[g+8][8nn+2t] CH[nn][3]=M[g+8][8nn+2t+1]   (fp32)

__device__ __forceinline__ uint32_t pack2(float e0, float e1) {
    uint32_t r;
    asm("cvt.rn.bf16x2.f32 %0, %1, %2;" : "=r"(r) : "f"(e1), "f"(e0));
    return r;
}
__device__ __forceinline__ void split_pair(float v0, float v1, uint32_t& hi, uint32_t& lo) {
    hi = pack2(v0, v1);
    float h0 = __uint_as_float(hi << 16);
    float h1 = __uint_as_float(hi & 0xFFFF0000u);
    lo = pack2(v0 - h0, v1 - h1);
}
__device__ __forceinline__ uint32_t prmt1(uint32_t a, uint32_t sel) {
    uint32_t r;
    asm("prmt.b32 %0, %1, %1, %2;" : "=r"(r) : "r"(a), "r"(sel));
    return r;
}
__device__ __forceinline__ void mma_bf16(float d[4], const uint32_t a[4],
                                         const uint32_t b[2], const float c[4]) {
    asm volatile(
        "mma.sync.aligned.m16n8k16.row.col.f32.bf16.bf16.f32 "
        "{%0,%1,%2,%3}, {%4,%5,%6,%7}, {%8,%9}, {%10,%11,%12,%13};"
        : "=f"(d[0]), "=f"(d[1]), "=f"(d[2]), "=f"(d[3])
        : "r"(a[0]), "r"(a[1]), "r"(a[2]), "r"(a[3]),
          "r"(b[0]), "r"(b[1]),
          "f"(c[0]), "f"(c[1]), "f"(c[2]), "f"(c[3]));
}
__device__ __forceinline__ float shfl(float v, int src) {
    return __shfl_sync(0xffffffffu, v, src);
}

// C-frag -> bf16 B-frags: b_kk needs M[2t+8kk+e][8nn+g], e=0,1; source lane
// 8t+q+4e, reg CH[nn][2kk+(g&1)]. Pre-staged shfl, then PRMT half-swap
// restores canonical (v0,v1) order for odd-g targets.
__device__ __forceinline__ void conv_to_B(const float CH[2][4], int idxA, int idxB,
                                          bool godd, uint32_t psel,
                                          uint32_t Bhi[2][2], uint32_t Blo[2][2]) {
#pragma unroll
    for (int nn = 0; nn < 2; nn++)
#pragma unroll
        for (int kk = 0; kk < 2; kk++) {
            float z1 = godd ? CH[nn][2 * kk + 1] : CH[nn][2 * kk];
            float s1 = shfl(z1, idxA);
            float z2 = godd ? CH[nn][2 * kk] : CH[nn][2 * kk + 1];
            float s2 = shfl(z2, idxB);
            uint32_t p = pack2(s1, s2);
            float d1 = s1 - __uint_as_float(p << 16);
            float d2 = s2 - __uint_as_float(p & 0xFFFF0000u);
            uint32_t qq = pack2(d1, d2);
            Bhi[nn][kk] = prmt1(p, psel);
            Blo[nn][kk] = prmt1(qq, psel);
        }
}

// Register transpose: TH = C-frag layout of M^T given CH of M (fp32).
__device__ __forceinline__ void transpose_frag(const float CH[2][4], int idxA, int idxB,
                                               bool godd, float TH[2][4]) {
#pragma unroll
    for (int nn = 0; nn < 2; nn++)
#pragma unroll
        for (int h = 0; h < 2; h++) {
            float z1 = godd ? CH[h][2 * nn + 1] : CH[h][2 * nn];
            float s1 = shfl(z1, idxA);
            float z2 = godd ? CH[h][2 * nn] : CH[h][2 * nn + 1];
            float s2 = shfl(z2, idxB);
            TH[nn][2 * h + 0] = godd ? s2 : s1;
            TH[nn][2 * h + 1] = godd ? s1 : s2;
        }
}

__device__ __forceinline__ float diag_partial(const float CH[2][4], bool isdiag, bool godd) {
    float e0 = godd ? CH[0][1] : CH[0][0];
    float e1 = godd ? CH[1][3] : CH[1][2];
    return isdiag ? (e0 + e1) : 0.f;
}

__device__ __forceinline__ float frag_dot(const float A[2][4], const float B[2][4]) {
    float s = 0.f;
#pragma unroll
    for (int nn = 0; nn < 2; nn++)
#pragma unroll
        for (int r = 0; r < 4; r++) s = fmaf(A[nn][r], B[nn][r], s);
    return s;
}

__device__ __forceinline__ void mm_chain(const uint32_t Ahi[4], const uint32_t Alo[4],
                                         const uint32_t Bhi[2][2], const uint32_t Blo[2][2],
                                         float D[2][4]) {
#pragma unroll
    for (int nn = 0; nn < 2; nn++) {
        float d[4] = {0.f, 0.f, 0.f, 0.f};
        mma_bf16(d, Ahi, Blo[nn], d);
        mma_bf16(d, Alo, Bhi[nn], d);
        mma_bf16(d, Ahi, Bhi[nn], d);
#pragma unroll
        for (int r = 0; r < 4; r++) D[nn][r] = d[r];
    }
}

__global__ void __launch_bounds__(128)
acoef_kernel(const float* __restrict__ x, const float* __restrict__ coef,
             float* __restrict__ out, int nsamples) {
    const int lane = threadIdx.x & 31;
    const int g = lane >> 2;
    const int t = lane & 3;
    const int q = g >> 1;
    const bool godd = (g & 1);
    const bool hi16 = (lane & 16);
    const bool isdiag = (t == q);
    const uint32_t psel = godd ? 0x1032u : 0x3210u;

    const int idxA_t = 8 * t + q + (godd ? 4 : 0);
    const int idxB_t = idxA_t ^ 4;

    const long sample = (long)blockIdx.x * (blockDim.x >> 5) + (threadIdx.x >> 5);
    if (sample >= nsamples) return;
    const float* gx = x + sample * 256;

    // ---- A(X): 4 x LDG.64 = the FULL matrix, coalesced; W = C-frag(X) ----
    float W[2][4];
    uint32_t AXhi[4], AXlo[4];
    {
        float2 p00 = __ldg((const float2*)(gx + g * 16 + 2 * t));
        float2 p10 = __ldg((const float2*)(gx + (g + 8) * 16 + 2 * t));
        float2 p01 = __ldg((const float2*)(gx + g * 16 + 2 * t + 8));
        float2 p11 = __ldg((const float2*)(gx + (g + 8) * 16 + 2 * t + 8));
        W[0][0] = p00.x; W[0][1] = p00.y; W[0][2] = p10.x; W[0][3] = p10.y;
        W[1][0] = p01.x; W[1][1] = p01.y; W[1][2] = p11.x; W[1][3] = p11.y;
        split_pair(p00.x, p00.y, AXhi[0], AXlo[0]);
        split_pair(p10.x, p10.y, AXhi[1], AXlo[1]);
        split_pair(p01.x, p01.y, AXhi[2], AXlo[2]);
        split_pair(p11.x, p11.y, AXhi[3], AXlo[3]);
    }
    // ---- B(X) = conv of W (C-frag(X)); no extra global loads ----
    uint32_t BXhi[2][2], BXlo[2][2];
    conv_to_B(W, idxA_t, idxB_t, godd, psel, BXhi, BXlo);

    float V[10];
    float C2[2][4], C3[2][4], C5[2][4], C6[2][4];
    float T3[2][4], T5[2][4];

    // mm1: x2 = X*X
    mm_chain(AXhi, AXlo, BXhi, BXlo, C2);
    V[0] = diag_partial(C2, isdiag, godd);          // tr2

    // B(x2) via conv; C2 stays live (tr7 = <T5,C2>)
    uint32_t Bc2hi[2][2], Bc2lo[2][2];
    conv_to_B(C2, idxA_t, idxB_t, godd, psel, Bc2hi, Bc2lo);

    // mm2: x3 = X*x2   (AX, BX dead after)
    mm_chain(AXhi, AXlo, Bc2hi, Bc2lo, C3);
    V[1] = diag_partial(C3, isdiag, godd);          // tr3

    // T3; tr4 = <W, T3>; W dead
    transpose_frag(C3, idxA_t, idxB_t, godd, T3);
    V[2] = frag_dot(W, T3);                         // tr4

    // A3 = in-lane repack of C3; Bc3 = in-lane repack of T3; C3 dead
    uint32_t A3hi[4], A3lo[4];
    split_pair(C3[0][0], C3[0][1], A3hi[0], A3lo[0]);
    split_pair(C3[0][2], C3[0][3], A3hi[1], A3lo[1]);
    split_pair(C3[1][0], C3[1][1], A3hi[2], A3lo[2]);
    split_pair(C3[1][2], C3[1][3], A3hi[3], A3lo[3]);
    uint32_t Bc3hi[2][2], Bc3lo[2][2];
    split_pair(T3[0][0], T3[0][1], Bc3hi[0][0], Bc3lo[0][0]);
    split_pair(T3[0][2], T3[0][3], Bc3hi[1][0], Bc3lo[1][0]);
    split_pair(T3[1][0], T3[1][1], Bc3hi[0][1], Bc3lo[0][1]);
    split_pair(T3[1][2], T3[1][3], Bc3hi[1][1], Bc3lo[1][1]);

    // mm3: x5 = x3*x2   (Bc2 dead after)
    mm_chain(A3hi, A3lo, Bc2hi, Bc2lo, C5);
    V[3] = diag_partial(C5, isdiag, godd);          // tr5
    V[6] = frag_dot(T3, C5);                        // tr8 = tr(x3*x5)

    // T5; tr7 = <T5, C2>; C2 dead before C6 is live
    transpose_frag(C5, idxA_t, idxB_t, godd, T5);
    V[5] = frag_dot(T5, C2);                        // tr7
    V[8] = frag_dot(T5, C5);                        // tr10 = tr(x5*x5)

    // mm4: x6 = x3*x3   (A3, Bc3 dead after)
    mm_chain(A3hi, A3lo, Bc3hi, Bc3lo, C6);
    V[4] = diag_partial(C6, isdiag, godd);          // tr6
    V[7] = frag_dot(T3, C6);                        // tr9 = tr(x3*x6); T3 dead
    V[9] = frag_dot(T5, C6);                        // tr11 = tr(x5*x6)

    // ---- 10-value reduce-scatter: 5/3/2/1/1 halving, 12 shfl ----
    const bool b8 = (lane & 8);
    const bool b4 = (lane & 4);
    const bool b2 = (lane & 2);
#pragma unroll
    for (int k = 0; k < 5; k++) {
        float send = hi16 ? V[k] : V[k + 5];
        float recv = __shfl_xor_sync(0xffffffffu, send, 16);
        V[k] = (hi16 ? V[k + 5] : V[k]) + recv;
    }
#pragma unroll
    for (int k = 0; k < 2; k++) {
        float send = b8 ? V[k] : V[k + 3];
        float recv = __shfl_xor_sync(0xffffffffu, send, 8);
        V[k] = (b8 ? V[k + 3] : V[k]) + recv;
    }
    {
        float recv = __shfl_xor_sync(0xffffffffu, V[2], 8);
        V[2] = V[2] + recv;   // valid in b8=0 lanes
    }
    {
        float send = b4 ? V[0] : (b8 ? V[1] : V[2]);
        float recv = __shfl_xor_sync(0xffffffffu, send, 4);
        float keep = b4 ? (b8 ? V[1] : V[2]) : V[0];
        V[0] = keep + recv;
    }
    {
        float recv = __shfl_xor_sync(0xffffffffu, V[1], 4);
        V[1] = V[1] + recv;   // valid in b8=0, b4=0 lanes
    }
    {
        const bool g00 = !b8 && !b4;
        float send = (g00 && !b2) ? V[1] : V[0];
        float recv = __shfl_xor_sync(0xffffffffu, send, 2);
        float keep = (g00 && b2) ? V[1] : V[0];
        V[0] = keep + recv;
    }
    V[0] += __shfl_xor_sync(0xffffffffu, V[0], 1);

    // ---- distributed polynomial: canonical lane per trace ----
    {
        const int i = (hi16 ? 5 : 0) + (b8 ? (b4 ? 4 : 3) : (b4 ? 2 : (b2 ? 1 : 0)));
        const bool active = ((lane & 1) == 0) &&
                            (((lane & 2) == 0) || ((lane & 12) == 0));
        const float4 cf = __ldg((const float4*)coef + i);
        const float u  = V[0] * (1.0f / 256.0f);
        const float u2 = u * u;
        float term = cf.x * u + cf.y * u2 + cf.z * (u2 * u) + cf.w * (u2 * u2);
        term *= __uint_as_float((uint32_t)(127 - 8 * i) << 23);   // 256^{-i}
        term = active ? term : 0.f;
        term += __shfl_xor_sync(0xffffffffu, term, 16);
        term += __shfl_xor_sync(0xffffffffu, term, 8);
        term += __shfl_xor_sync(0xffffffffu, term, 4);
        term += __shfl_xor_sync(0xffffffffu, term, 2);
        if (lane == 0) out[sample] = term;
    }
}

extern "C" void kernel_launch(void* const* d_in, const int* in_sizes, int n_in,
                              void* d_out, int out_size) {
    const float* x;
    const float* coef;
    if (n_in >= 2 && in_sizes[0] == 40) {
        coef = (const float*)d_in[0];
        x    = (const float*)d_in[1];
    } else {
        x    = (const float*)d_in[0];
        coef = (const float*)d_in[1];
    }
    float* out = (float*)d_out;
    int nsamples = out_size;
    const int warps_per_cta = 4;
    int grid = (nsamples + warps_per_cta - 1) / warps_per_cta;
    acoef_kernel<<<grid, warps_per_cta * 32>>>(x, coef, out, nsamples);
}

// round 17
// speedup vs baseline: 1.1068x; 1.0966x over previous
#include <cuda_runtime.h>
#include <cstdint>

// ACoef: per-sample traces of x^2..x^11 for 65536 16x16 fp32 matrices,
// out[b] = sum_{i,j} coef[i][j] * tr_{i+2}^(j+1) / 256^(i+j+1).
//
// One sample per WARP, bf16 m16n8k16 mma, 3xBF16 compensation
// (AhiBlo + AloBhi + AhiBhi), 6 mma per matmul.
// R17: powers of X commute, so reorder the chain to make every operand an
// in-lane repack except ONE conv (B(X)) and TWO transposes:
//   mm1: x2 = X  * X    A=split(W),  B=conv(W)     [conv]
//   mm2: x3 = x2 * X    A=split(C2), B(X) reused   (x2*X == X*x2)
//   mm3: x5 = x2 * x3   A(x2) reused, B=split(T3)
//   mm4: x6 = x3 * x3   A=split(C3), B(x3) reused
// The Bc2 conversion of R16 is deleted: 32->24 shfl, -16 alu, and mm2's
// dependence on mm1 shrinks to a 6-op in-lane split.
// Traces: tr2,3,5,6 = diag(C2,C3,C5,C6); tr4=<W,T3>; tr7=<T5,C2>;
// tr8=<T3,C5>; tr9=<T3,C6>; tr10=<T5,C5>; tr11=<T5,C6>.
//
// bf16 m16n8k16 fragments (lane: g=lane>>2, t=lane&3):
//   A: a0={A[g][2t],..} a1={A[g+8][2t],..} a2={A[g][2t+8],..} a3={A[g+8][2t+8],..}
//   B: b_kk={B[2t+8kk][8nn+g],B[2t+8kk+1][8nn+g]}  (col-major)
//   C: CH[nn][0]=M[g][8nn+2t] CH[nn][1]=M[g][8nn+2t+1]
//      CH[nn][2]=M[g+8][8nn+2t] CH[nn][3]=M[g+8][8nn+2t+1]   (fp32)
// In-lane identities: A-frag(M) = pairs of C-frag(M);
//                     B-frag(M) = pairs of C-frag(M^T).

__device__ __forceinline__ uint32_t pack2(float e0, float e1) {
    uint32_t r;
    asm("cvt.rn.bf16x2.f32 %0, %1, %2;" : "=r"(r) : "f"(e1), "f"(e0));
    return r;
}
__device__ __forceinline__ void split_pair(float v0, float v1, uint32_t& hi, uint32_t& lo) {
    hi = pack2(v0, v1);
    float h0 = __uint_as_float(hi << 16);
    float h1 = __uint_as_float(hi & 0xFFFF0000u);
    lo = pack2(v0 - h0, v1 - h1);
}
__device__ __forceinline__ uint32_t prmt1(uint32_t a, uint32_t sel) {
    uint32_t r;
    asm("prmt.b32 %0, %1, %1, %2;" : "=r"(r) : "r"(a), "r"(sel));
    return r;
}
__device__ __forceinline__ void mma_bf16(float d[4], const uint32_t a[4],
                                         const uint32_t b[2], const float c[4]) {
    asm volatile(
        "mma.sync.aligned.m16n8k16.row.col.f32.bf16.bf16.f32 "
        "{%0,%1,%2,%3}, {%4,%5,%6,%7}, {%8,%9}, {%10,%11,%12,%13};"
        : "=f"(d[0]), "=f"(d[1]), "=f"(d[2]), "=f"(d[3])
        : "r"(a[0]), "r"(a[1]), "r"(a[2]), "r"(a[3]),
          "r"(b[0]), "r"(b[1]),
          "f"(c[0]), "f"(c[1]), "f"(c[2]), "f"(c[3]));
}
__device__ __forceinline__ float shfl(float v, int src) {
    return __shfl_sync(0xffffffffu, v, src);
}

// C-frag -> bf16 B-frags via shuffles (used ONCE, for B(X)).
__device__ __forceinline__ void conv_to_B(const float CH[2][4], int idxA, int idxB,
                                          bool godd, uint32_t psel,
                                          uint32_t Bhi[2][2], uint32_t Blo[2][2]) {
#pragma unroll
    for (int nn = 0; nn < 2; nn++)
#pragma unroll
        for (int kk = 0; kk < 2; kk++) {
            float z1 = godd ? CH[nn][2 * kk + 1] : CH[nn][2 * kk];
            float s1 = shfl(z1, idxA);
            float z2 = godd ? CH[nn][2 * kk] : CH[nn][2 * kk + 1];
            float s2 = shfl(z2, idxB);
            uint32_t p = pack2(s1, s2);
            float d1 = s1 - __uint_as_float(p << 16);
            float d2 = s2 - __uint_as_float(p & 0xFFFF0000u);
            uint32_t qq = pack2(d1, d2);
            Bhi[nn][kk] = prmt1(p, psel);
            Blo[nn][kk] = prmt1(qq, psel);
        }
}

// Register transpose: TH = C-frag layout of M^T given CH of M (fp32).
__device__ __forceinline__ void transpose_frag(const float CH[2][4], int idxA, int idxB,
                                               bool godd, float TH[2][4]) {
#pragma unroll
    for (int nn = 0; nn < 2; nn++)
#pragma unroll
        for (int h = 0; h < 2; h++) {
            float z1 = godd ? CH[h][2 * nn + 1] : CH[h][2 * nn];
            float s1 = shfl(z1, idxA);
            float z2 = godd ? CH[h][2 * nn] : CH[h][2 * nn + 1];
            float s2 = shfl(z2, idxB);
            TH[nn][2 * h + 0] = godd ? s2 : s1;
            TH[nn][2 * h + 1] = godd ? s1 : s2;
        }
}

__device__ __forceinline__ float diag_partial(const float CH[2][4], bool isdiag, bool godd) {
    float e0 = godd ? CH[0][1] : CH[0][0];
    float e1 = godd ? CH[1][3] : CH[1][2];
    return isdiag ? (e0 + e1) : 0.f;
}

__device__ __forceinline__ float frag_dot(const float A[2][4], const float B[2][4]) {
    float s = 0.f;
#pragma unroll
    for (int nn = 0; nn < 2; nn++)
#pragma unroll
        for (int r = 0; r < 4; r++) s = fmaf(A[nn][r], B[nn][r], s);
    return s;
}

// In-lane A-frag (bf16 hi/lo) from a C-frag.
__device__ __forceinline__ void make_A(const float CH[2][4], uint32_t Ahi[4], uint32_t Alo[4]) {
    split_pair(CH[0][0], CH[0][1], Ahi[0], Alo[0]);
    split_pair(CH[0][2], CH[0][3], Ahi[1], Alo[1]);
    split_pair(CH[1][0], CH[1][1], Ahi[2], Alo[2]);
    split_pair(CH[1][2], CH[1][3], Ahi[3], Alo[3]);
}
// In-lane B-frag (bf16 hi/lo) from the TRANSPOSED C-frag.
__device__ __forceinline__ void make_B(const float TH[2][4], uint32_t Bhi[2][2], uint32_t Blo[2][2]) {
    split_pair(TH[0][0], TH[0][1], Bhi[0][0], Blo[0][0]);
    split_pair(TH[0][2], TH[0][3], Bhi[1][0], Blo[1][0]);
    split_pair(TH[1][0], TH[1][1], Bhi[0][1], Blo[0][1]);
    split_pair(TH[1][2], TH[1][3], Bhi[1][1], Blo[1][1]);
}

__device__ __forceinline__ void mm_chain(const uint32_t Ahi[4], const uint32_t Alo[4],
                                         const uint32_t Bhi[2][2], const uint32_t Blo[2][2],
                                         float D[2][4]) {
#pragma unroll
    for (int nn = 0; nn < 2; nn++) {
        float d[4] = {0.f, 0.f, 0.f, 0.f};
        mma_bf16(d, Ahi, Blo[nn], d);
        mma_bf16(d, Alo, Bhi[nn], d);
        mma_bf16(d, Ahi, Bhi[nn], d);
#pragma unroll
        for (int r = 0; r < 4; r++) D[nn][r] = d[r];
    }
}

__global__ void __launch_bounds__(128)
acoef_kernel(const float* __restrict__ x, const float* __restrict__ coef,
             float* __restrict__ out, int nsamples) {
    const int lane = threadIdx.x & 31;
    const int g = lane >> 2;
    const int t = lane & 3;
    const int q = g >> 1;
    const bool godd = (g & 1);
    const bool hi16 = (lane & 16);
    const bool isdiag = (t == q);
    const uint32_t psel = godd ? 0x1032u : 0x3210u;

    const int idxA_t = 8 * t + q + (godd ? 4 : 0);
    const int idxB_t = idxA_t ^ 4;

    const long sample = (long)blockIdx.x * (blockDim.x >> 5) + (threadIdx.x >> 5);
    if (sample >= nsamples) return;
    const float* gx = x + sample * 256;

    // ---- load X once, coalesced: W = C-frag(X); A(X) = in-lane split ----
    float W[2][4];
    uint32_t AXhi[4], AXlo[4];
    {
        float2 p00 = __ldg((const float2*)(gx + g * 16 + 2 * t));
        float2 p10 = __ldg((const float2*)(gx + (g + 8) * 16 + 2 * t));
        float2 p01 = __ldg((const float2*)(gx + g * 16 + 2 * t + 8));
        float2 p11 = __ldg((const float2*)(gx + (g + 8) * 16 + 2 * t + 8));
        W[0][0] = p00.x; W[0][1] = p00.y; W[0][2] = p10.x; W[0][3] = p10.y;
        W[1][0] = p01.x; W[1][1] = p01.y; W[1][2] = p11.x; W[1][3] = p11.y;
        split_pair(p00.x, p00.y, AXhi[0], AXlo[0]);
        split_pair(p10.x, p10.y, AXhi[1], AXlo[1]);
        split_pair(p01.x, p01.y, AXhi[2], AXlo[2]);
        split_pair(p11.x, p11.y, AXhi[3], AXlo[3]);
    }
    // ---- B(X) = conv of W (the ONLY shuffle conversion) ----
    uint32_t BXhi[2][2], BXlo[2][2];
    conv_to_B(W, idxA_t, idxB_t, godd, psel, BXhi, BXlo);

    float V[10];
    float C2[2][4], C3[2][4], C5[2][4], C6[2][4];
    float T3[2][4], T5[2][4];

    // mm1: x2 = X*X
    mm_chain(AXhi, AXlo, BXhi, BXlo, C2);
    V[0] = diag_partial(C2, isdiag, godd);          // tr2

    // A(x2) in-lane; AX dead after mm2
    uint32_t A2hi[4], A2lo[4];
    make_A(C2, A2hi, A2lo);

    // mm2: x3 = x2*X  (== X*x2; BX reused, then dead)
    mm_chain(A2hi, A2lo, BXhi, BXlo, C3);
    V[1] = diag_partial(C3, isdiag, godd);          // tr3

    // T3; tr4 = <W,T3>; W dead
    transpose_frag(C3, idxA_t, idxB_t, godd, T3);
    V[2] = frag_dot(W, T3);                         // tr4

    // B(x3) in-lane from T3
    uint32_t B3hi[2][2], B3lo[2][2];
    make_B(T3, B3hi, B3lo);

    // mm3: x5 = x2*x3  (A2 dead after)
    mm_chain(A2hi, A2lo, B3hi, B3lo, C5);
    V[3] = diag_partial(C5, isdiag, godd);          // tr5
    V[6] = frag_dot(T3, C5);                        // tr8 = tr(x3*x5)

    // T5; tr7 = <T5,C2>; C2 dead before C6 is live
    transpose_frag(C5, idxA_t, idxB_t, godd, T5);
    V[5] = frag_dot(T5, C2);                        // tr7
    V[8] = frag_dot(T5, C5);                        // tr10 = tr(x5*x5)

    // A(x3) in-lane; mm4: x6 = x3*x3  (A3, B3 dead after)
    uint32_t A3hi[4], A3lo[4];
    make_A(C3, A3hi, A3lo);
    mm_chain(A3hi, A3lo, B3hi, B3lo, C6);
    V[4] = diag_partial(C6, isdiag, godd);          // tr6
    V[7] = frag_dot(T3, C6);                        // tr9 = tr(x3*x6); T3 dead
    V[9] = frag_dot(T5, C6);                        // tr11 = tr(x5*x6)

    // ---- 10-value reduce-scatter: 5/3/2/1/1 halving, 12 shfl ----
    const bool b8 = (lane & 8);
    const bool b4 = (lane & 4);
    const bool b2 = (lane & 2);
#pragma unroll
    for (int k = 0; k < 5; k++) {
        float send = hi16 ? V[k] : V[k + 5];
        float recv = __shfl_xor_sync(0xffffffffu, send, 16);
        V[k] = (hi16 ? V[k + 5] : V[k]) + recv;
    }
#pragma unroll
    for (int k = 0; k < 2; k++) {
        float send = b8 ? V[k] : V[k + 3];
        float recv = __shfl_xor_sync(0xffffffffu, send, 8);
        V[k] = (b8 ? V[k + 3] : V[k]) + recv;
    }
    {
        float recv = __shfl_xor_sync(0xffffffffu, V[2], 8);
        V[2] = V[2] + recv;   // valid in b8=0 lanes
    }
    {
        float send = b4 ? V[0] : (b8 ? V[1] : V[2]);
        float recv = __shfl_xor_sync(0xffffffffu, send, 4);
        float keep = b4 ? (b8 ? V[1] : V[2]) : V[0];
        V[0] = keep + recv;
    }
    {
        float recv = __shfl_xor_sync(0xffffffffu, V[1], 4);
        V[1] = V[1] + recv;   // valid in b8=0, b4=0 lanes
    }
    {
        const bool g00 = !b8 && !b4;
        float send = (g00 && !b2) ? V[1] : V[0];
        float recv = __shfl_xor_sync(0xffffffffu, send, 2);
        float keep = (g00 && b2) ? V[1] : V[0];
        V[0] = keep + recv;
    }
    V[0] += __shfl_xor_sync(0xffffffffu, V[0], 1);

    // ---- distributed polynomial: canonical lane per trace ----
    {
        const int i = (hi16 ? 5 : 0) + (b8 ? (b4 ? 4 : 3) : (b4 ? 2 : (b2 ? 1 : 0)));
        const bool active = ((lane & 1) == 0) &&
                            (((lane & 2) == 0) || ((lane & 12) == 0));
        const float4 cf = __ldg((const float4*)coef + i);
        const float u  = V[0] * (1.0f / 256.0f);
        const float u2 = u * u;
        float term = cf.x * u + cf.y * u2 + cf.z * (u2 * u) + cf.w * (u2 * u2);
        term *= __uint_as_float((uint32_t)(127 - 8 * i) << 23);   // 256^{-i}
        term = active ? term : 0.f;
        term += __shfl_xor_sync(0xffffffffu, term, 16);
        term += __shfl_xor_sync(0xffffffffu, term, 8);
        term += __shfl_xor_sync(0xffffffffu, term, 4);
        term += __shfl_xor_sync(0xffffffffu, term, 2);
        if (lane == 0) out[sample] = term;
    }
}

extern "C" void kernel_launch(void* const* d_in, const int* in_sizes, int n_in,
                              void* d_out, int out_size) {
    const float* x;
    const float* coef;
    if (n_in >= 2 && in_sizes[0] == 40) {
        coef = (const float*)d_in[0];
        x    = (const float*)d_in[1];
    } else {
        x    = (const float*)d_in[0];
        coef = (const float*)d_in[1];
    }
    float* out = (float*)d_out;
    int nsamples = out_size;
    const int warps_per_cta = 4;
    int grid = (nsamples + warps_per_cta - 1) / warps_per_cta;
    acoef_kernel<<<grid, warps_per_cta * 32>>>(x, coef, out, nsamples);
}